// round 5
// baseline (speedup 1.0000x reference)
#include <cuda_runtime.h>

// ---------------- problem constants ----------------
#define NA 3
#define GH 52
#define GW 52
#define NCLS 80
#define PLANE (GH*GW)             // 2704 = 13 * 208
#define EPSF 1e-7f
#define LOG1MEPS 1.00000011686097e-07f   // -log(1 - 1e-7)
#define CHUNK 208                 // cells per block (PLANE = 13*208, 208 % 4 == 0)
#define NCHUNK 13
#define TPB 64
#define NWARP 2
#define NF4 (CHUNK/4)             // 52
#define NSLOT 32

// scaled anchors = ANCHORS / (416/52) = ANCHORS / 8
__constant__ float c_aw[3] = {1.25f, 2.0f, 4.125f};
__constant__ float c_ah[3] = {1.625f, 3.75f, 2.875f};

// ---------------- slotted global accumulators (zero at module load; reset by last block)
__device__ double       d_acc[NSLOT][4];   // iou, conf1, conf2, cls
__device__ int          d_npos[NSLOT];
__device__ unsigned int d_count;

__device__ __forceinline__ float warp_sum(float v) {
#pragma unroll
    for (int o = 16; o > 0; o >>= 1) v += __shfl_down_sync(0xffffffffu, v, o);
    return v;
}

__device__ __forceinline__ float fsigmoid(float x) {
    return __fdividef(1.0f, 1.0f + __expf(-x));
}

__global__ void __launch_bounds__(TPB) k_fused(const float* __restrict__ input,
                                               const float* __restrict__ targets,
                                               float* __restrict__ out,
                                               int B, int T) {
    // block -> (b, a, chunk)
    int bx    = blockIdx.x;
    int b     = bx / (NA * NCHUNK);
    int rem   = bx % (NA * NCHUNK);
    int a     = rem / NCHUNK;
    int chunk = rem % NCHUNK;
    int p0    = chunk * CHUNK;

    size_t plane_base = ((size_t)b * 255 + (size_t)a * 85) * PLANE;

    int tid = threadIdx.x;
    int wid = tid >> 5, lid = tid & 31;

    // ---- issue conf load FIRST (independent of decode; overlaps both waves) ----
    float4 cv = make_float4(0.f, 0.f, 0.f, 0.f);
    if (tid < NF4)
        cv = *reinterpret_cast<const float4*>(
            input + plane_base + (size_t)4 * PLANE + p0 + 4 * tid);

    __shared__ int           s_win[CHUNK];
    __shared__ unsigned int  s_cls[CHUNK * 3];
    __shared__ unsigned char s_ign[CHUNK];
    __shared__ int           s_mlist[64];
    __shared__ int           s_nmask;
    __shared__ float         s_part[5][NWARP];
    __shared__ int           s_last;

    for (int k = tid; k < CHUNK; k += TPB) { s_win[k] = -1; s_ign[k] = 0; }
    for (int k = tid; k < 3 * CHUNK; k += TPB) s_cls[k] = 0u;
    if (tid == 0) s_nmask = 0;
    __syncthreads();

    // ---- in-block target decode (T <= 64 covered in one pass) ----
    for (int t = tid; t < T; t += TPB) {
        const float* tp = targets + ((size_t)b * T + t) * 5;
        float c = tp[0], x = tp[1], y = tp[2], w = tp[3], h = tp[4];
        if (c + x + y + w + h == 0.0f) continue;          // valid = sum != 0

        float gx = x * GW, gy = y * GH, gw = w * GW, gh = h * GH;
        int gi = (int)gx, gj = (int)gy;
        if (gi < 0 || gi >= GW || gj < 0 || gj >= GH) continue;

        int p  = gj * GW + gi;
        int lp = p - p0;
        if (lp < 0 || lp >= CHUNK) continue;

        float area = gw * gh;
        float ious[3];
        float best_iou = -1.0f;
        int best = 0;
#pragma unroll
        for (int k = 0; k < 3; k++) {
            float inter = fminf(gw, c_aw[k]) * fminf(gh, c_ah[k]);
            float iou = inter / (area + c_aw[k] * c_ah[k] - inter + 1e-16f);
            ious[k] = iou;
            if (iou > best_iou) { best_iou = iou; best = k; } // argmax (first max)
        }

        if (ious[a] > 0.5f) s_ign[lp] = 1;                 // benign races
        if (best == a) {
            atomicMax(&s_win[lp], t);                      // last-update-wins
            int cls = (int)c;
            if (cls >= 0 && cls < NCLS)
                atomicOr(&s_cls[lp + ((cls >> 5) * CHUNK)], 1u << (cls & 31));
        }
    }
    __syncthreads();

    float a_iou = 0.f, a_c1 = 0.f, a_c2 = 0.f, a_cl = 0.f, a_np = 0.f;

    // ---- dense conf consume + masked-list build ----
    if (tid < NF4) {
        float cl[4] = {cv.x, cv.y, cv.z, cv.w};
#pragma unroll
        for (int k = 0; k < 4; k++) {
            int lp = 4 * tid + k;
            float conf   = fsigmoid(cl[k]);
            float conf_c = fminf(fmaxf(conf, EPSF), 1.0f - EPSF);
            bool m   = (s_win[lp] >= 0);
            bool ign = (s_ign[lp] != 0);
            a_c1 += m      ? (-__logf(conf_c))        : LOG1MEPS;
            a_c2 += (!ign) ? (-__logf(1.0f - conf_c)) : LOG1MEPS;
            if (m) {
                int idx = atomicAdd(&s_nmask, 1);
                if (idx < 64) s_mlist[idx] = lp;
            }
        }
    }
    __syncthreads();

    // ---- masked cells: one warp per cell, lanes cover the 85 channels ----
    int nmask = min(s_nmask, 64);
    for (int m = wid; m < nmask; m += NWARP) {
        int lp = s_mlist[m];
        int p  = p0 + lp;
        int j  = p / GW;
        int i  = p - j * GW;
        int wt = s_win[lp];
        size_t base = plane_base + p;

        float v0 = input[base + (size_t)lid * PLANE];
        float v1 = input[base + (size_t)(lid + 32) * PLANE];
        float v2 = (lid < 21) ? input[base + (size_t)(lid + 64) * PLANE] : 0.0f;

        float xl = __shfl_sync(0xffffffffu, v0, 0);
        float yl = __shfl_sync(0xffffffffu, v0, 1);
        float wl = __shfl_sync(0xffffffffu, v0, 2);
        float hl = __shfl_sync(0xffffffffu, v0, 3);

        const float* tp = targets + ((size_t)b * T + wt) * 5;
        float kx = tp[1] * GW, ky = tp[2] * GH;
        float kw = tp[3] * GW, kh = tp[4] * GH;

        float hx = fsigmoid(xl) + (float)i;
        float hy = fsigmoid(yl) + (float)j;
        float hw = __expf(wl) * c_aw[a];
        float hh = __expf(hl) * c_ah[a];

        float iw = fminf(hx + hw * 0.5f, kx + kw * 0.5f) -
                   fmaxf(hx - hw * 0.5f, kx - kw * 0.5f);
        iw = fmaxf(iw, 0.0f);
        float ih = fminf(hy + hh * 0.5f, ky + kh * 0.5f) -
                   fmaxf(hy - hh * 0.5f, ky - kh * 0.5f);
        ih = fmaxf(ih, 0.0f);
        float inter = iw * ih;
        float iou = inter / (hw * hh + kw * kh - inter + 1e-16f);
        if (lid == 0) { a_iou += 1.0f - iou; a_np += 1.0f; }

        unsigned w0 = s_cls[lp];
        unsigned w1 = s_cls[lp + CHUNK];
        unsigned w2 = s_cls[lp + 2 * CHUNK];

        float cls_sum = 0.0f;
        if (lid >= 5) {
            int c = lid - 5;                       // classes 0..26 from v0
            float pp = fminf(fmaxf(fsigmoid(v0), EPSF), 1.0f - EPSF);
            bool tt = (w0 >> c) & 1u;
            cls_sum += -__logf(tt ? pp : 1.0f - pp);
        }
        {
            int c = lid + 27;                      // classes 27..58 from v1
            float pp = fminf(fmaxf(fsigmoid(v1), EPSF), 1.0f - EPSF);
            unsigned word = (c < 32) ? w0 : (c < 64 ? w1 : w2);
            bool tt = (word >> (c & 31)) & 1u;
            cls_sum += -__logf(tt ? pp : 1.0f - pp);
        }
        if (lid < 21) {
            int c = lid + 59;                      // classes 59..79 from v2
            float pp = fminf(fmaxf(fsigmoid(v2), EPSF), 1.0f - EPSF);
            bool tt = (w2 >> (c & 31)) & 1u;
            cls_sum += -__logf(tt ? pp : 1.0f - pp);
        }
        a_cl += cls_sum;
    }

    // ---- block reduction (2 warps) ----
    a_iou = warp_sum(a_iou);
    a_c1  = warp_sum(a_c1);
    a_c2  = warp_sum(a_c2);
    a_cl  = warp_sum(a_cl);
    a_np  = warp_sum(a_np);

    if (lid == 0) {
        s_part[0][wid] = a_iou; s_part[1][wid] = a_c1; s_part[2][wid] = a_c2;
        s_part[3][wid] = a_cl;  s_part[4][wid] = a_np;
    }
    __syncthreads();
    if (tid == 0) {
        int slot = bx & (NSLOT - 1);
        float v0 = s_part[0][0] + s_part[0][1];
        float v1 = s_part[1][0] + s_part[1][1];
        float v2 = s_part[2][0] + s_part[2][1];
        float v3 = s_part[3][0] + s_part[3][1];
        float v4 = s_part[4][0] + s_part[4][1];
        if (v0 != 0.f) atomicAdd(&d_acc[slot][0], (double)v0);
        atomicAdd(&d_acc[slot][1], (double)v1);
        atomicAdd(&d_acc[slot][2], (double)v2);
        if (v3 != 0.f) atomicAdd(&d_acc[slot][3], (double)v3);
        if (v4 != 0.f) atomicAdd(&d_npos[slot], (int)(v4 + 0.5f));
    }

    // ---- last-block finalize + reset (graph-replay safe) ----
    __threadfence();
    if (tid == 0) {
        unsigned prev = atomicAdd(&d_count, 1u);
        s_last = (prev == gridDim.x - 1) ? 1 : 0;
    }
    __syncthreads();
    if (s_last && tid == 0) {
        double iou = 0.0, c1 = 0.0, c2 = 0.0, cls = 0.0;
        int np = 0;
#pragma unroll
        for (int s = 0; s < NSLOT; s++) {
            iou += d_acc[s][0]; c1 += d_acc[s][1];
            c2  += d_acc[s][2]; cls += d_acc[s][3];
            np  += d_npos[s];
            d_acc[s][0] = 0.0; d_acc[s][1] = 0.0;
            d_acc[s][2] = 0.0; d_acc[s][3] = 0.0;
            d_npos[s] = 0;
        }
        double N = (double)B * NA * GH * GW;
        float loss_iou  = (float)iou;
        float loss_conf = (float)(c1 / N + 0.5 * (c2 / N));
        double npf = (np < 1) ? 1.0 : (double)np;
        float loss_cls  = (float)(cls / (npf * (double)NCLS));
        out[0] = 0.5f * loss_iou + loss_conf + loss_cls;
        out[1] = loss_iou;
        out[2] = loss_conf;
        out[3] = loss_cls;
        d_count = 0u;
    }
}

extern "C" void kernel_launch(void* const* d_in, const int* in_sizes, int n_in,
                              void* d_out, int out_size) {
    const float* input   = (const float*)d_in[0];
    const float* targets = (const float*)d_in[1];

    int B = in_sizes[0] / (255 * GH * GW);
    int T = in_sizes[1] / (B * 5);

    int nblk = B * NA * NCHUNK;   // 32*3*13 = 1248
    k_fused<<<nblk, TPB>>>(input, targets, (float*)d_out, B, T);
}

// round 6
// speedup vs baseline: 1.7496x; 1.7496x over previous
#include <cuda_runtime.h>

// ---------------- problem constants ----------------
#define NA 3
#define GH 52
#define GW 52
#define NCLS 80
#define PLANE (GH*GW)             // 2704
#define EPSF 1e-7f
#define LOG1MEPS 1.00000011686097e-07f   // -log(1 - 1e-7)
#define XCLIP 16.118095f          // log((1-EPS)/EPS): sigmoid(±XCLIP) = 1-EPS / EPS
#define CHUNK 1024                // cells per block
#define NCHUNK 3                  // 1024+1024+656
#define TPB 256
#define NWARP 8
#define NSLOT 32

// scaled anchors = ANCHORS / (416/52) = ANCHORS / 8
__constant__ float c_aw[3] = {1.25f, 2.0f, 4.125f};
__constant__ float c_ah[3] = {1.625f, 3.75f, 2.875f};

// ---------------- slotted global accumulators (zero at load; reset by last block) ----
__device__ double       d_acc[NSLOT][4];   // iou, conf1, conf2, cls
__device__ int          d_npos[NSLOT];
__device__ unsigned int d_count;

__device__ __forceinline__ float warp_sum(float v) {
#pragma unroll
    for (int o = 16; o > 0; o >>= 1) v += __shfl_down_sync(0xffffffffu, v, o);
    return v;
}

__device__ __forceinline__ float fsigmoid(float x) {
    return __fdividef(1.0f, 1.0f + __expf(-x));
}

// L(x) = log(1 + exp(-x)) = -log(sigmoid(x)); clamped to replicate EPS clipping
__device__ __forceinline__ float softplus_neg(float xc) {
    return __logf(1.0f + __expf(-xc));
}

__global__ void __launch_bounds__(TPB) k_fused(const float* __restrict__ input,
                                               const float* __restrict__ targets,
                                               float* __restrict__ out,
                                               int B, int T) {
    // block -> (b, a, chunk)
    int bx    = blockIdx.x;
    int b     = bx / (NA * NCHUNK);
    int rem   = bx % (NA * NCHUNK);
    int a     = rem / NCHUNK;
    int chunk = rem % NCHUNK;
    int p0    = chunk * CHUNK;
    int ncell = min(PLANE - p0, CHUNK);     // 1024 or 656
    int nf4   = ncell >> 2;

    size_t plane_base = ((size_t)b * 255 + (size_t)a * 85) * PLANE;

    int tid = threadIdx.x;
    int wid = tid >> 5, lid = tid & 31;

    // ---- issue conf load FIRST (independent of decode) ----
    float4 cv = make_float4(0.f, 0.f, 0.f, 0.f);
    if (tid < nf4)
        cv = *reinterpret_cast<const float4*>(
            input + plane_base + (size_t)4 * PLANE + p0 + 4 * tid);

    __shared__ int           s_win[CHUNK];
    __shared__ unsigned int  s_cls[CHUNK * 3];
    __shared__ unsigned char s_ign[CHUNK];
    __shared__ int           s_mlist[64];
    __shared__ int           s_nmask;
    __shared__ float         s_part[5][NWARP];
    __shared__ int           s_last;

#pragma unroll
    for (int u = 0; u < CHUNK / TPB; u++) {
        int k = tid + u * TPB;
        s_win[k] = -1;
        s_ign[k] = 0;
        s_cls[k] = 0u;
        s_cls[k + CHUNK] = 0u;
        s_cls[k + 2 * CHUNK] = 0u;
    }
    if (tid == 0) s_nmask = 0;
    __syncthreads();

    // ---- in-block target decode ----
    for (int t = tid; t < T; t += TPB) {
        const float* tp = targets + ((size_t)b * T + t) * 5;
        float c = tp[0], x = tp[1], y = tp[2], w = tp[3], h = tp[4];
        if (c + x + y + w + h == 0.0f) continue;          // valid = sum != 0

        float gx = x * GW, gy = y * GH, gw = w * GW, gh = h * GH;
        int gi = (int)gx, gj = (int)gy;
        if (gi < 0 || gi >= GW || gj < 0 || gj >= GH) continue;

        int p  = gj * GW + gi;
        int lp = p - p0;
        if (lp < 0 || lp >= ncell) continue;

        float area = gw * gh;
        float ious[3];
        float best_iou = -1.0f;
        int best = 0;
#pragma unroll
        for (int k = 0; k < 3; k++) {
            float inter = fminf(gw, c_aw[k]) * fminf(gh, c_ah[k]);
            float iou = inter / (area + c_aw[k] * c_ah[k] - inter + 1e-16f);
            ious[k] = iou;
            if (iou > best_iou) { best_iou = iou; best = k; } // argmax (first max)
        }

        if (ious[a] > 0.5f) s_ign[lp] = 1;                 // benign races
        if (best == a) {
            atomicMax(&s_win[lp], t);                      // last-update-wins
            int cls = (int)c;
            if (cls >= 0 && cls < NCLS)
                atomicOr(&s_cls[lp + ((cls >> 5) * CHUNK)], 1u << (cls & 31));
        }
    }
    __syncthreads();

    float a_iou = 0.f, a_c1 = 0.f, a_c2 = 0.f, a_cl = 0.f, a_np = 0.f;

    // ---- dense conf consume (softplus identity: 1 EX2 + 1 LG2 for BOTH bce terms) ----
    if (tid < nf4) {
        float cl[4] = {cv.x, cv.y, cv.z, cv.w};
#pragma unroll
        for (int k = 0; k < 4; k++) {
            int lp = 4 * tid + k;
            float xc = fminf(fmaxf(cl[k], -XCLIP), XCLIP);
            float L  = softplus_neg(xc);            // -log(sigmoid)
            bool m   = (s_win[lp] >= 0);
            bool ign = (s_ign[lp] != 0);
            a_c1 += m      ? L          : LOG1MEPS; // bce(conf*mask, mask)
            a_c2 += (!ign) ? (L + xc)   : LOG1MEPS; // bce(conf*noobj, 0) = -log(1-sig)
            if (m) {
                int idx = atomicAdd(&s_nmask, 1);
                if (idx < 64) s_mlist[idx] = lp;
            }
        }
    }
    __syncthreads();

    // ---- masked cells: one warp per cell, lanes cover the 85 channels ----
    int nmask = min(s_nmask, 64);
    for (int m = wid; m < nmask; m += NWARP) {
        int lp = s_mlist[m];
        int p  = p0 + lp;
        int j  = p / GW;
        int i  = p - j * GW;
        int wt = s_win[lp];
        size_t base = plane_base + p;

        float v0 = input[base + (size_t)lid * PLANE];
        float v1 = input[base + (size_t)(lid + 32) * PLANE];
        float v2 = (lid < 21) ? input[base + (size_t)(lid + 64) * PLANE] : 0.0f;

        float xl = __shfl_sync(0xffffffffu, v0, 0);
        float yl = __shfl_sync(0xffffffffu, v0, 1);
        float wl = __shfl_sync(0xffffffffu, v0, 2);
        float hl = __shfl_sync(0xffffffffu, v0, 3);

        const float* tp = targets + ((size_t)b * T + wt) * 5;
        float kx = tp[1] * GW, ky = tp[2] * GH;
        float kw = tp[3] * GW, kh = tp[4] * GH;

        float hx = fsigmoid(xl) + (float)i;
        float hy = fsigmoid(yl) + (float)j;
        float hw = __expf(wl) * c_aw[a];
        float hh = __expf(hl) * c_ah[a];

        float iw = fminf(hx + hw * 0.5f, kx + kw * 0.5f) -
                   fmaxf(hx - hw * 0.5f, kx - kw * 0.5f);
        iw = fmaxf(iw, 0.0f);
        float ih = fminf(hy + hh * 0.5f, ky + kh * 0.5f) -
                   fmaxf(hy - hh * 0.5f, ky - kh * 0.5f);
        ih = fmaxf(ih, 0.0f);
        float inter = iw * ih;
        float iou = inter / (hw * hh + kw * kh - inter + 1e-16f);
        if (lid == 0) { a_iou += 1.0f - iou; a_np += 1.0f; }

        unsigned w0 = s_cls[lp];
        unsigned w1 = s_cls[lp + CHUNK];
        unsigned w2 = s_cls[lp + 2 * CHUNK];

        // class bce via softplus: t ? L(v) : L(v)+v  (1 EX2 + 1 LG2 per class)
        float cls_sum = 0.0f;
        if (lid >= 5) {
            int c = lid - 5;                       // classes 0..26 from v0
            float vc = fminf(fmaxf(v0, -XCLIP), XCLIP);
            float L  = softplus_neg(vc);
            bool tt = (w0 >> c) & 1u;
            cls_sum += tt ? L : (L + vc);
        }
        {
            int c = lid + 27;                      // classes 27..58 from v1
            float vc = fminf(fmaxf(v1, -XCLIP), XCLIP);
            float L  = softplus_neg(vc);
            unsigned word = (c < 32) ? w0 : (c < 64 ? w1 : w2);
            bool tt = (word >> (c & 31)) & 1u;
            cls_sum += tt ? L : (L + vc);
        }
        if (lid < 21) {
            int c = lid + 59;                      // classes 59..79 from v2
            float vc = fminf(fmaxf(v2, -XCLIP), XCLIP);
            float L  = softplus_neg(vc);
            bool tt = (w2 >> (c & 31)) & 1u;
            cls_sum += tt ? L : (L + vc);
        }
        a_cl += cls_sum;
    }

    // ---- block reduction (8 warps) ----
    a_iou = warp_sum(a_iou);
    a_c1  = warp_sum(a_c1);
    a_c2  = warp_sum(a_c2);
    a_cl  = warp_sum(a_cl);
    a_np  = warp_sum(a_np);

    if (lid == 0) {
        s_part[0][wid] = a_iou; s_part[1][wid] = a_c1; s_part[2][wid] = a_c2;
        s_part[3][wid] = a_cl;  s_part[4][wid] = a_np;
    }
    __syncthreads();
    if (wid == 0) {
        float v0 = (lid < NWARP) ? s_part[0][lid] : 0.f;
        float v1 = (lid < NWARP) ? s_part[1][lid] : 0.f;
        float v2 = (lid < NWARP) ? s_part[2][lid] : 0.f;
        float v3 = (lid < NWARP) ? s_part[3][lid] : 0.f;
        float v4 = (lid < NWARP) ? s_part[4][lid] : 0.f;
        v0 = warp_sum(v0); v1 = warp_sum(v1); v2 = warp_sum(v2);
        v3 = warp_sum(v3); v4 = warp_sum(v4);
        if (lid == 0) {
            int slot = bx & (NSLOT - 1);
            if (v0 != 0.f) atomicAdd(&d_acc[slot][0], (double)v0);
            atomicAdd(&d_acc[slot][1], (double)v1);
            atomicAdd(&d_acc[slot][2], (double)v2);
            if (v3 != 0.f) atomicAdd(&d_acc[slot][3], (double)v3);
            if (v4 != 0.f) atomicAdd(&d_npos[slot], (int)(v4 + 0.5f));
        }
    }

    // ---- last-block finalize + reset (graph-replay safe) ----
    __threadfence();
    if (tid == 0) {
        unsigned prev = atomicAdd(&d_count, 1u);
        s_last = (prev == gridDim.x - 1) ? 1 : 0;
    }
    __syncthreads();
    if (s_last && tid == 0) {
        double iou = 0.0, c1 = 0.0, c2 = 0.0, cls = 0.0;
        int np = 0;
#pragma unroll
        for (int s = 0; s < NSLOT; s++) {
            iou += d_acc[s][0]; c1 += d_acc[s][1];
            c2  += d_acc[s][2]; cls += d_acc[s][3];
            np  += d_npos[s];
            d_acc[s][0] = 0.0; d_acc[s][1] = 0.0;
            d_acc[s][2] = 0.0; d_acc[s][3] = 0.0;
            d_npos[s] = 0;
        }
        double N = (double)B * NA * GH * GW;
        float loss_iou  = (float)iou;
        float loss_conf = (float)(c1 / N + 0.5 * (c2 / N));
        double npf = (np < 1) ? 1.0 : (double)np;
        float loss_cls  = (float)(cls / (npf * (double)NCLS));
        out[0] = 0.5f * loss_iou + loss_conf + loss_cls;
        out[1] = loss_iou;
        out[2] = loss_conf;
        out[3] = loss_cls;
        d_count = 0u;
    }
}

extern "C" void kernel_launch(void* const* d_in, const int* in_sizes, int n_in,
                              void* d_out, int out_size) {
    const float* input   = (const float*)d_in[0];
    const float* targets = (const float*)d_in[1];

    int B = in_sizes[0] / (255 * GH * GW);
    int T = in_sizes[1] / (B * 5);

    int nblk = B * NA * NCHUNK;   // 32*3*3 = 288
    k_fused<<<nblk, TPB>>>(input, targets, (float*)d_out, B, T);
}

// round 7
// speedup vs baseline: 2.5749x; 1.4717x over previous
#include <cuda_runtime.h>

// ---------------- problem constants ----------------
#define NA 3
#define GH 52
#define GW 52
#define NCLS 80
#define PLANE (GH*GW)             // 2704
#define EPSF 1e-7f
#define LOG1MEPS 1.00000011686097e-07f   // -log(1 - 1e-7)
#define XCLIP 16.118095f          // log((1-EPS)/EPS): sigmoid(+-XCLIP) = 1-EPS / EPS
#define CHUNK 1024                // cells per block (multiple of 4)
#define NCHUNK 3                  // 1024+1024+656 = 2704
#define TPB 256
#define NWARP (TPB/32)

// scaled anchors = ANCHORS / (416/52) = ANCHORS / 8
__constant__ float c_aw[3] = {1.25f, 2.0f, 4.125f};
__constant__ float c_ah[3] = {1.625f, 3.75f, 2.875f};

// ---------------- global accumulators (zero at module load; reset by last block) ----
__device__ double       d_acc[4];     // iou_sum, conf1_sum, conf2_sum, cls_sum
__device__ int          d_npos;
__device__ unsigned int d_count;

__device__ __forceinline__ float warp_sum(float v) {
#pragma unroll
    for (int o = 16; o > 0; o >>= 1) v += __shfl_down_sync(0xffffffffu, v, o);
    return v;
}

__device__ __forceinline__ float fsigmoid(float x) {
    return __fdividef(1.0f, 1.0f + __expf(-x));
}

// L(x) = log(1 + exp(-x)) = -log(sigmoid(x)); input pre-clamped to +-XCLIP
__device__ __forceinline__ float softplus_neg(float xc) {
    return __logf(1.0f + __expf(-xc));
}

__global__ void k_fused(const float* __restrict__ input,
                        const float* __restrict__ targets,
                        float* __restrict__ out,
                        int B, int T) {
    // block -> (b, a, chunk)
    int bx    = blockIdx.x;
    int b     = bx / (NA * NCHUNK);
    int rem   = bx % (NA * NCHUNK);
    int a     = rem / NCHUNK;
    int chunk = rem % NCHUNK;
    int p0    = chunk * CHUNK;
    int ncell = min(PLANE - p0, CHUNK);     // 1024 or 656

    __shared__ int           s_win[CHUNK];        // winner target idx, -1 none
    __shared__ unsigned int  s_cls[CHUNK * 3];    // 80-bit class union
    __shared__ unsigned char s_ign[CHUNK];        // 1 => noobj = 0
    __shared__ int           s_mlist[64];         // masked-cell local indices
    __shared__ int           s_nmask;
    __shared__ float         s_part[5][NWARP];
    __shared__ int           s_last;

    int tid = threadIdx.x;
#pragma unroll
    for (int u = 0; u < CHUNK / TPB; u++) {
        int k = tid + u * TPB;
        s_win[k] = -1;
        s_ign[k] = 0;
        s_cls[k] = 0u;
        s_cls[k + CHUNK] = 0u;
        s_cls[k + 2 * CHUNK] = 0u;
    }
    if (tid == 0) s_nmask = 0;
    __syncthreads();

    // ---- in-block target decode ----
    for (int t = tid; t < T; t += TPB) {
        const float* tp = targets + ((size_t)b * T + t) * 5;
        float c = tp[0], x = tp[1], y = tp[2], w = tp[3], h = tp[4];
        if (c + x + y + w + h == 0.0f) continue;          // valid = sum != 0

        float gx = x * GW, gy = y * GH, gw = w * GW, gh = h * GH;
        int gi = (int)gx, gj = (int)gy;
        if (gi < 0 || gi >= GW || gj < 0 || gj >= GH) continue;

        int p  = gj * GW + gi;
        int lp = p - p0;
        if (lp < 0 || lp >= ncell) continue;

        float area = gw * gh;
        float ious[3];
        float best_iou = -1.0f;
        int best = 0;
#pragma unroll
        for (int k = 0; k < 3; k++) {
            float inter = fminf(gw, c_aw[k]) * fminf(gh, c_ah[k]);
            float iou = inter / (area + c_aw[k] * c_ah[k] - inter + 1e-16f);
            ious[k] = iou;
            if (iou > best_iou) { best_iou = iou; best = k; } // argmax (first max)
        }

        if (ious[a] > 0.5f) s_ign[lp] = 1;                 // benign races
        if (best == a) {
            atomicMax(&s_win[lp], t);                      // last-update-wins
            int cls = (int)c;
            if (cls >= 0 && cls < NCLS)
                atomicOr(&s_cls[lp + ((cls >> 5) * CHUNK)], 1u << (cls & 31));
        }
    }
    __syncthreads();

    float a_iou = 0.f, a_c1 = 0.f, a_c2 = 0.f, a_cl = 0.f, a_np = 0.f;
    size_t plane_base = ((size_t)b * 255 + (size_t)a * 85) * PLANE;

    // ---- dense conf sweep (float4) via softplus: 1 EX2 + 1 LG2 gives both bce terms ----
    int nf4 = ncell >> 2;                     // 256 or 164
    if (tid < nf4) {
        const float4 cv = *reinterpret_cast<const float4*>(
            input + plane_base + (size_t)4 * PLANE + p0 + 4 * tid);
        float cl[4] = {cv.x, cv.y, cv.z, cv.w};
#pragma unroll
        for (int k = 0; k < 4; k++) {
            int lp = 4 * tid + k;
            float xc = fminf(fmaxf(cl[k], -XCLIP), XCLIP);
            float L  = softplus_neg(xc);            // = -log(clip(sigmoid))
            bool m   = (s_win[lp] >= 0);
            bool ign = (s_ign[lp] != 0);
            a_c1 += m      ? L        : LOG1MEPS;   // bce(conf*mask, mask)
            a_c2 += (!ign) ? (L + xc) : LOG1MEPS;   // bce(conf*noobj, 0) = -log(1-sig)
            if (m) {
                int idx = atomicAdd(&s_nmask, 1);
                if (idx < 64) s_mlist[idx] = lp;
            }
        }
    }
    __syncthreads();

    // ---- masked cells: one warp per cell, lanes cover channels ----
    int wid = tid >> 5, lid = tid & 31;
    int nmask = min(s_nmask, 64);
    for (int m = wid; m < nmask; m += NWARP) {
        int lp = s_mlist[m];
        int p  = p0 + lp;
        int j  = p / GW;
        int i  = p - j * GW;
        int wt = s_win[lp];
        size_t base = plane_base + p;

        // lane l loads channels l, l+32, l+64 (all concurrent)
        float v0 = input[base + (size_t)lid * PLANE];
        float v1 = input[base + (size_t)(lid + 32) * PLANE];
        float v2 = (lid < 21) ? input[base + (size_t)(lid + 64) * PLANE] : 0.0f;

        // broadcast x,y,w,h logits from lanes 0..3
        float xl = __shfl_sync(0xffffffffu, v0, 0);
        float yl = __shfl_sync(0xffffffffu, v0, 1);
        float wl = __shfl_sync(0xffffffffu, v0, 2);
        float hl = __shfl_sync(0xffffffffu, v0, 3);

        const float* tp = targets + ((size_t)b * T + wt) * 5;
        float kx = tp[1] * GW, ky = tp[2] * GH;
        float kw = tp[3] * GW, kh = tp[4] * GH;

        float hx = fsigmoid(xl) + (float)i;
        float hy = fsigmoid(yl) + (float)j;
        float hw = __expf(wl) * c_aw[a];
        float hh = __expf(hl) * c_ah[a];

        float iw = fminf(hx + hw * 0.5f, kx + kw * 0.5f) -
                   fmaxf(hx - hw * 0.5f, kx - kw * 0.5f);
        iw = fmaxf(iw, 0.0f);
        float ih = fminf(hy + hh * 0.5f, ky + kh * 0.5f) -
                   fmaxf(hy - hh * 0.5f, ky - kh * 0.5f);
        ih = fmaxf(ih, 0.0f);
        float inter = iw * ih;
        float iou = inter / (hw * hh + kw * kh - inter + 1e-16f);
        if (lid == 0) { a_iou += 1.0f - iou; a_np += 1.0f; }

        unsigned w0 = s_cls[lp];
        unsigned w1 = s_cls[lp + CHUNK];
        unsigned w2 = s_cls[lp + 2 * CHUNK];

        // class bce via softplus: t ? L(v) : L(v)+v
        float cls_sum = 0.0f;
        if (lid >= 5) {
            int c = lid - 5;                       // classes 0..26 from v0
            float vc = fminf(fmaxf(v0, -XCLIP), XCLIP);
            float L  = softplus_neg(vc);
            bool tt = (w0 >> c) & 1u;
            cls_sum += tt ? L : (L + vc);
        }
        {
            int c = lid + 27;                      // classes 27..58 from v1
            float vc = fminf(fmaxf(v1, -XCLIP), XCLIP);
            float L  = softplus_neg(vc);
            unsigned word = (c < 32) ? w0 : (c < 64 ? w1 : w2);
            bool tt = (word >> (c & 31)) & 1u;
            cls_sum += tt ? L : (L + vc);
        }
        if (lid < 21) {
            int c = lid + 59;                      // classes 59..79 from v2
            float vc = fminf(fmaxf(v2, -XCLIP), XCLIP);
            float L  = softplus_neg(vc);
            bool tt = (w2 >> (c & 31)) & 1u;
            cls_sum += tt ? L : (L + vc);
        }
        a_cl += cls_sum;   // warp-reduced below
    }

    // ---- block reduction ----
    a_iou = warp_sum(a_iou);
    a_c1  = warp_sum(a_c1);
    a_c2  = warp_sum(a_c2);
    a_cl  = warp_sum(a_cl);
    a_np  = warp_sum(a_np);

    if (lid == 0) {
        s_part[0][wid] = a_iou; s_part[1][wid] = a_c1; s_part[2][wid] = a_c2;
        s_part[3][wid] = a_cl;  s_part[4][wid] = a_np;
    }
    __syncthreads();
    if (wid == 0) {
        float v0 = (lid < NWARP) ? s_part[0][lid] : 0.f;
        float v1 = (lid < NWARP) ? s_part[1][lid] : 0.f;
        float v2 = (lid < NWARP) ? s_part[2][lid] : 0.f;
        float v3 = (lid < NWARP) ? s_part[3][lid] : 0.f;
        float v4 = (lid < NWARP) ? s_part[4][lid] : 0.f;
        v0 = warp_sum(v0); v1 = warp_sum(v1); v2 = warp_sum(v2);
        v3 = warp_sum(v3); v4 = warp_sum(v4);
        if (lid == 0) {
            if (v0 != 0.f) atomicAdd(&d_acc[0], (double)v0);
            atomicAdd(&d_acc[1], (double)v1);
            atomicAdd(&d_acc[2], (double)v2);
            if (v3 != 0.f) atomicAdd(&d_acc[3], (double)v3);
            if (v4 != 0.f) atomicAdd(&d_npos, (int)(v4 + 0.5f));
        }
    }

    // ---- last-block finalize + reset (graph-replay safe) ----
    __threadfence();
    if (tid == 0) {
        unsigned prev = atomicAdd(&d_count, 1u);
        s_last = (prev == gridDim.x - 1) ? 1 : 0;
    }
    __syncthreads();
    if (s_last && tid == 0) {
        double iou = d_acc[0], c1 = d_acc[1], c2 = d_acc[2], cls = d_acc[3];
        int np = d_npos;
        double N = (double)B * NA * GH * GW;
        float loss_iou  = (float)iou;
        float loss_conf = (float)(c1 / N + 0.5 * (c2 / N));
        double npf = (np < 1) ? 1.0 : (double)np;
        float loss_cls  = (float)(cls / (npf * (double)NCLS));
        out[0] = 0.5f * loss_iou + loss_conf + loss_cls;
        out[1] = loss_iou;
        out[2] = loss_conf;
        out[3] = loss_cls;
        d_acc[0] = 0.0; d_acc[1] = 0.0; d_acc[2] = 0.0; d_acc[3] = 0.0;
        d_npos = 0;
        d_count = 0u;
    }
}

extern "C" void kernel_launch(void* const* d_in, const int* in_sizes, int n_in,
                              void* d_out, int out_size) {
    const float* input   = (const float*)d_in[0];
    const float* targets = (const float*)d_in[1];

    int B = in_sizes[0] / (255 * GH * GW);
    int T = in_sizes[1] / (B * 5);

    int nblk = B * NA * NCHUNK;   // 32*3*3 = 288
    k_fused<<<nblk, TPB>>>(input, targets, (float*)d_out, B, T);
}